// round 13
// baseline (speedup 1.0000x reference)
#include <cuda_runtime.h>
#include <cuda_fp16.h>
#include <cstdint>

#define BATCH 8
#define SEQ 2048
#define DIN 4096
#define DOUT 4096
#define RANK 16
#define NADAPT 8
#define MROWS (BATCH * SEQ)   // 16384

// GEMM tiling: 128x128 CTA tile, 512 threads (16 warps of 32x32), 2 CTAs/SM
#define BM 128
#define BN 128
#define BK 64
#define NITER (DIN / BK)      // 64
#define ROWB 144              // 64 fp16 = 128B data + 16B pad
#define A_OFF 0
#define B_OFF 18432           // 128*144
#define STAGE 36864           // + 128*144
#define NSTAGE 3
#define SMEM_TOTAL (NSTAGE * STAGE)   // 110592/CTA -> 2 CTAs = 221184/SM
#define WSCALE 64.0f
#define WSCALE_INV 0.015625f

// ---------------- device scratch (no cudaMalloc allowed) -------------------
__device__ int    g_adapter[BATCH];
__device__ float  g_inter[(size_t)MROWS * RANK];
__device__ __half g_xh[(size_t)MROWS * DIN];
__device__ __half g_wh[(size_t)DOUT * DIN];

// ---------------- PTX helpers ----------------------------------------------
__device__ __forceinline__ uint32_t smem_u32(const void* p) {
    uint32_t a;
    asm("{ .reg .u64 t; cvta.to.shared.u64 t, %1; cvt.u32.u64 %0, t; }"
        : "=r"(a) : "l"(p));
    return a;
}
__device__ __forceinline__ void cp_async16(uint32_t dst, const void* src) {
    asm volatile("cp.async.cg.shared.global [%0], [%1], 16;"
                 :: "r"(dst), "l"(src) : "memory");
}
#define CP_COMMIT() asm volatile("cp.async.commit_group;" ::: "memory")
#define CP_WAIT(N)  asm volatile("cp.async.wait_group %0;" :: "n"(N) : "memory")

#define LDSM4(r, addr) \
    asm volatile("ldmatrix.sync.aligned.m8n8.x4.shared.b16 {%0,%1,%2,%3}, [%4];" \
                 : "=r"((r)[0]), "=r"((r)[1]), "=r"((r)[2]), "=r"((r)[3]) \
                 : "r"(addr))

#define MMA(d, a, b0, b1) \
    asm volatile("mma.sync.aligned.m16n8k16.row.col.f32.f16.f16.f32 " \
                 "{%0,%1,%2,%3}, {%4,%5,%6,%7}, {%8,%9}, {%0,%1,%2,%3};" \
                 : "+f"((d)[0]), "+f"((d)[1]), "+f"((d)[2]), "+f"((d)[3]) \
                 : "r"((a)[0]), "r"((a)[1]), "r"((a)[2]), "r"((a)[3]), \
                   "r"(b0), "r"(b1))

__device__ __forceinline__ uint32_t pack_half2(__half a, __half b) {
    return (uint32_t)__half_as_ushort(a) | ((uint32_t)__half_as_ushort(b) << 16);
}

// ---------------------------------------------------------------------------
// Setup: normalize adapter indices (int64 or int32, robustly)
// ---------------------------------------------------------------------------
__global__ void setup_adapters_kernel(const int* __restrict__ idx_raw) {
    if (threadIdx.x != 0 || blockIdx.x != 0) return;
    bool is64 = true;
    #pragma unroll
    for (int b = 0; b < BATCH; b++) {
        int lo = idx_raw[2 * b];
        int hi = idx_raw[2 * b + 1];
        if (hi != 0 || lo < 0 || lo >= NADAPT) { is64 = false; break; }
    }
    #pragma unroll
    for (int b = 0; b < BATCH; b++) {
        int v = is64 ? idx_raw[2 * b] : idx_raw[b];
        if (v < 0) v = 0;
        if (v >= NADAPT) v = NADAPT - 1;
        g_adapter[b] = v;
    }
}

// ---------------------------------------------------------------------------
// W*64 -> fp16
// ---------------------------------------------------------------------------
__global__ __launch_bounds__(256) void convert_w_kernel(const float* __restrict__ W) {
    size_t base = ((size_t)blockIdx.x * 256 + threadIdx.x) * 8;
    float4 a = *(const float4*)(W + base);
    float4 b = *(const float4*)(W + base + 4);
    uint32_t p[4];
    p[0] = pack_half2(__float2half_rn(a.x * WSCALE), __float2half_rn(a.y * WSCALE));
    p[1] = pack_half2(__float2half_rn(a.z * WSCALE), __float2half_rn(a.w * WSCALE));
    p[2] = pack_half2(__float2half_rn(b.x * WSCALE), __float2half_rn(b.y * WSCALE));
    p[3] = pack_half2(__float2half_rn(b.z * WSCALE), __float2half_rn(b.w * WSCALE));
    *(uint4*)(g_wh + base) = make_uint4(p[0], p[1], p[2], p[3]);
}

// ---------------------------------------------------------------------------
// Fused: x -> fp16 (g_xh) AND inter[m][r] = sum_k x[m][k]*a[r][k] (exact fp32)
// Each warp handles 4 m-rows: As LDS reads amortized over 4 rows.
// ---------------------------------------------------------------------------
__global__ __launch_bounds__(256) void prep_x_kernel(
    const float* __restrict__ x,
    const float* __restrict__ lora_a)
{
    __shared__ float As[RANK][128];
    const int m0 = blockIdx.x * 32;
    const int adapter = g_adapter[m0 >> 11];
    const float* A = lora_a + (size_t)adapter * RANK * DIN;

    const int warp = threadIdx.x >> 5;
    const int lane = threadIdx.x & 31;
    const int m = m0 + warp * 4;

    float acc[4][RANK];
    #pragma unroll
    for (int w = 0; w < 4; w++)
        #pragma unroll
        for (int r = 0; r < RANK; r++) acc[w][r] = 0.0f;

    for (int k0 = 0; k0 < DIN; k0 += 128) {
        __syncthreads();
        #pragma unroll
        for (int i = threadIdx.x; i < 512; i += 256) {
            int rr = i >> 5;
            int c4 = i & 31;
            *(float4*)&As[rr][c4 * 4] =
                *(const float4*)(A + (size_t)rr * DIN + k0 + c4 * 4);
        }
        __syncthreads();

        float4 xv[4];
        #pragma unroll
        for (int w = 0; w < 4; w++) {
            xv[w] = *(const float4*)(x + (size_t)(m + w) * DIN + k0 + lane * 4);
            uint2 h = make_uint2(
                pack_half2(__float2half_rn(xv[w].x), __float2half_rn(xv[w].y)),
                pack_half2(__float2half_rn(xv[w].z), __float2half_rn(xv[w].w)));
            *(uint2*)(g_xh + (size_t)(m + w) * DIN + k0 + lane * 4) = h;
        }

        #pragma unroll
        for (int r = 0; r < RANK; r++) {
            float4 av = *(const float4*)&As[r][lane * 4];
            #pragma unroll
            for (int w = 0; w < 4; w++)
                acc[w][r] += xv[w].x * av.x + xv[w].y * av.y
                           + xv[w].z * av.z + xv[w].w * av.w;
        }
    }

    #pragma unroll
    for (int r = 0; r < RANK; r++) {
        float v0 = acc[0][r], v1 = acc[1][r], v2 = acc[2][r], v3 = acc[3][r];
        #pragma unroll
        for (int off = 16; off > 0; off >>= 1) {
            v0 += __shfl_xor_sync(0xffffffffu, v0, off);
            v1 += __shfl_xor_sync(0xffffffffu, v1, off);
            v2 += __shfl_xor_sync(0xffffffffu, v2, off);
            v3 += __shfl_xor_sync(0xffffffffu, v3, off);
        }
        if (lane == r) {
            g_inter[(size_t)m * RANK + r] = v0;
            g_inter[(size_t)(m + 1) * RANK + r] = v1;
            g_inter[(size_t)(m + 2) * RANK + r] = v2;
            g_inter[(size_t)(m + 3) * RANK + r] = v3;
        }
    }
}

// ---------------------------------------------------------------------------
// HMMA GEMM: out = (x_h @ W_h^T)/64 + LoRA + bias
// 128x128 CTA tile, 512 threads: 16 warps of 32x32, BK=64, 3-stage pipeline,
// 2 CTAs/SM -> 32 warps (8/SMSP) to hide LDSM/MMA scoreboard stalls.
// ---------------------------------------------------------------------------
__global__ __launch_bounds__(512, 2) void gemm_hmma_kernel(
    const float* __restrict__ bias,
    const float* __restrict__ lora_b,
    float* __restrict__ out)
{
    extern __shared__ char smem[];
    const uint32_t sbase = smem_u32(smem);
    const int tid  = threadIdx.x;
    const int lane = tid & 31;
    const int warp = tid >> 5;
    const int wm = warp & 3;          // 4 warps along M (32 each)
    const int wn = warp >> 2;         // 4 warps along N (32 each)
    const int n0 = blockIdx.x * BN;
    const int m0 = blockIdx.y * BM;

    const __half* Ax = g_xh + (size_t)m0 * DIN;
    const __half* Bx = g_wh + (size_t)n0 * DIN;

    // per-thread ldmatrix base offsets
    const uint32_t aoff = (uint32_t)((wm * 32 + (lane & 15)) * ROWB + (lane >> 4) * 16);
    const uint32_t boff = (uint32_t)((wn * 32 + (lane & 7) + ((lane >> 4) & 1) * 8) * ROWB
                                     + ((lane >> 3) & 1) * 16);

    float c[2][4][4];
    #pragma unroll
    for (int i = 0; i < 2; i++)
        #pragma unroll
        for (int j = 0; j < 4; j++)
            #pragma unroll
            for (int q = 0; q < 4; q++) c[i][j][q] = 0.0f;

    auto issue = [&](int it) {
        uint32_t st = sbase + (it % NSTAGE) * STAGE;
        int k0 = it * BK;
        #pragma unroll
        for (int i = 0; i < 2; i++) {               // A: 1024 chunks of 16B
            int id = tid + i * 512;
            int row = id >> 3, cc = id & 7;
            uint32_t d = st + row * ROWB + cc * 16;
            cp_async16(d + A_OFF, Ax + (size_t)row * DIN + k0 + cc * 8);
        }
        #pragma unroll
        for (int i = 0; i < 2; i++) {               // B: 1024 chunks of 16B
            int id = tid + i * 512;
            int row = id >> 3, cc = id & 7;
            uint32_t d = st + row * ROWB + cc * 16;
            cp_async16(d + B_OFF, Bx + (size_t)row * DIN + k0 + cc * 8);
        }
    };

    issue(0); CP_COMMIT();
    issue(1); CP_COMMIT();

    #pragma unroll 1
    for (int it = 0; it < NITER; it++) {
        CP_WAIT(1);
        __syncthreads();
        if (it + 2 < NITER) { issue(it + 2); CP_COMMIT(); }

        const uint32_t st = sbase + (it % NSTAGE) * STAGE;
        #pragma unroll
        for (int kk = 0; kk < 4; kk++) {
            uint32_t bh[2][4], af[2][4];
            #pragma unroll
            for (int nt = 0; nt < 2; nt++)
                LDSM4(bh[nt], st + B_OFF + boff + nt * (16 * ROWB) + kk * 32);
            #pragma unroll
            for (int i = 0; i < 2; i++)
                LDSM4(af[i], st + A_OFF + aoff + i * (16 * ROWB) + kk * 32);
            #pragma unroll
            for (int i = 0; i < 2; i++)
                #pragma unroll
                for (int nt = 0; nt < 2; nt++) {
                    MMA(c[i][2*nt],   af[i], bh[nt][0], bh[nt][1]);
                    MMA(c[i][2*nt+1], af[i], bh[nt][2], bh[nt][3]);
                }
        }
    }

    // ---- undo W scaling ----
    #pragma unroll
    for (int i = 0; i < 2; i++)
        #pragma unroll
        for (int j = 0; j < 4; j++)
            #pragma unroll
            for (int q = 0; q < 4; q++) c[i][j][q] *= WSCALE_INV;

    // ---- LoRA epilogue (exact fp32, rank 16) ----
    const int r0 = lane >> 2;
    const int cq = (lane & 3) * 2;
    const int adapter = g_adapter[m0 >> 11];
    const float* lbp = lora_b + ((size_t)adapter * DOUT + n0) * RANK;

    #pragma unroll
    for (int r = 0; r < RANK; r++) {
        float av[2][2];
        #pragma unroll
        for (int i = 0; i < 2; i++)
            #pragma unroll
            for (int h = 0; h < 2; h++)
                av[i][h] = __ldg(&g_inter[(size_t)(m0 + wm*32 + i*16 + h*8 + r0) * RANK + r]);
        float bv[4][2];
        #pragma unroll
        for (int j = 0; j < 4; j++) {
            int nl = wn * 32 + j * 8 + cq;
            bv[j][0] = __ldg(&lbp[(size_t)nl * RANK + r]);
            bv[j][1] = __ldg(&lbp[(size_t)(nl + 1) * RANK + r]);
        }
        #pragma unroll
        for (int i = 0; i < 2; i++)
            #pragma unroll
            for (int j = 0; j < 4; j++) {
                c[i][j][0] += av[i][0] * bv[j][0];
                c[i][j][1] += av[i][0] * bv[j][1];
                c[i][j][2] += av[i][1] * bv[j][0];
                c[i][j][3] += av[i][1] * bv[j][1];
            }
    }

    // ---- bias + writeback ----
    #pragma unroll
    for (int j = 0; j < 4; j++) {
        int n = n0 + wn * 32 + j * 8 + cq;
        float b0 = __ldg(bias + n);
        float b1 = __ldg(bias + n + 1);
        #pragma unroll
        for (int i = 0; i < 2; i++) {
            int m = m0 + wm * 32 + i * 16 + r0;
            *(float2*)(out + (size_t)m * DOUT + n) =
                make_float2(c[i][j][0] + b0, c[i][j][1] + b1);
            *(float2*)(out + (size_t)(m + 8) * DOUT + n) =
                make_float2(c[i][j][2] + b0, c[i][j][3] + b1);
        }
    }
}

// ---------------------------------------------------------------------------
extern "C" void kernel_launch(void* const* d_in, const int* in_sizes, int n_in,
                              void* d_out, int out_size) {
    const float* x       = (const float*)d_in[0];
    const float* W       = (const float*)d_in[1];
    const float* bias    = (const float*)d_in[2];
    const float* lora_a  = (const float*)d_in[3];
    const float* lora_b  = (const float*)d_in[4];
    const int*   idx_raw = (const int*)d_in[5];
    float* out = (float*)d_out;

    cudaFuncSetAttribute(gemm_hmma_kernel,
                         cudaFuncAttributeMaxDynamicSharedMemorySize, SMEM_TOTAL);

    setup_adapters_kernel<<<1, 1>>>(idx_raw);
    convert_w_kernel<<<(int)(((size_t)DOUT * DIN) / 2048), 256>>>(W);
    prep_x_kernel<<<MROWS / 32, 256>>>(x, lora_a);

    dim3 grid(DOUT / BN, MROWS / BM);   // (32, 128): N fastest -> X reuse, W streams
    gemm_hmma_kernel<<<grid, 512, SMEM_TOTAL>>>(bias, lora_b, out);
}

// round 14
// speedup vs baseline: 1.0680x; 1.0680x over previous
#include <cuda_runtime.h>
#include <cuda_fp16.h>
#include <cstdint>

#define BATCH 8
#define SEQ 2048
#define DIN 4096
#define DOUT 4096
#define RANK 16
#define NADAPT 8
#define MROWS (BATCH * SEQ)   // 16384

// GEMM tiling: 128x128 CTA tile, 2 CTAs per SM (R12 config — measured best)
#define BM 128
#define BN 128
#define BK 64
#define NITER (DIN / BK)      // 64
#define ROWB 144              // 64 fp16 = 128B data + 16B pad
#define A_OFF 0
#define B_OFF 18432           // 128*144
#define STAGE 36864           // + 128*144
#define NSTAGE 3
#define SMEM_TOTAL (NSTAGE * STAGE)   // 110592/CTA -> 2 CTAs = 221184/SM
#define WSCALE 64.0f
#define WSCALE_INV 0.015625f

// ---------------- device scratch (no cudaMalloc allowed) -------------------
__device__ int    g_adapter[BATCH];
__device__ float  g_inter[(size_t)MROWS * RANK];
__device__ __half g_xh[(size_t)MROWS * DIN];
__device__ __half g_wh[(size_t)DOUT * DIN];

// ---------------- PTX helpers ----------------------------------------------
__device__ __forceinline__ uint32_t smem_u32(const void* p) {
    uint32_t a;
    asm("{ .reg .u64 t; cvta.to.shared.u64 t, %1; cvt.u32.u64 %0, t; }"
        : "=r"(a) : "l"(p));
    return a;
}
__device__ __forceinline__ void cp_async16(uint32_t dst, const void* src) {
    asm volatile("cp.async.cg.shared.global [%0], [%1], 16;"
                 :: "r"(dst), "l"(src) : "memory");
}
#define CP_COMMIT() asm volatile("cp.async.commit_group;" ::: "memory")
#define CP_WAIT(N)  asm volatile("cp.async.wait_group %0;" :: "n"(N) : "memory")

#define LDSM4(r, addr) \
    asm volatile("ldmatrix.sync.aligned.m8n8.x4.shared.b16 {%0,%1,%2,%3}, [%4];" \
                 : "=r"((r)[0]), "=r"((r)[1]), "=r"((r)[2]), "=r"((r)[3]) \
                 : "r"(addr))

#define MMA(d, a, b0, b1) \
    asm volatile("mma.sync.aligned.m16n8k16.row.col.f32.f16.f16.f32 " \
                 "{%0,%1,%2,%3}, {%4,%5,%6,%7}, {%8,%9}, {%0,%1,%2,%3};" \
                 : "+f"((d)[0]), "+f"((d)[1]), "+f"((d)[2]), "+f"((d)[3]) \
                 : "r"((a)[0]), "r"((a)[1]), "r"((a)[2]), "r"((a)[3]), \
                   "r"(b0), "r"(b1))

__device__ __forceinline__ uint32_t pack_half2(__half a, __half b) {
    return (uint32_t)__half_as_ushort(a) | ((uint32_t)__half_as_ushort(b) << 16);
}

// ---------------------------------------------------------------------------
// Setup: normalize adapter indices (int64 or int32, robustly)
// ---------------------------------------------------------------------------
__global__ void setup_adapters_kernel(const int* __restrict__ idx_raw) {
    if (threadIdx.x != 0 || blockIdx.x != 0) return;
    bool is64 = true;
    #pragma unroll
    for (int b = 0; b < BATCH; b++) {
        int lo = idx_raw[2 * b];
        int hi = idx_raw[2 * b + 1];
        if (hi != 0 || lo < 0 || lo >= NADAPT) { is64 = false; break; }
    }
    #pragma unroll
    for (int b = 0; b < BATCH; b++) {
        int v = is64 ? idx_raw[2 * b] : idx_raw[b];
        if (v < 0) v = 0;
        if (v >= NADAPT) v = NADAPT - 1;
        g_adapter[b] = v;
    }
}

// ---------------------------------------------------------------------------
// W*64 -> fp16
// ---------------------------------------------------------------------------
__global__ __launch_bounds__(256) void convert_w_kernel(const float* __restrict__ W) {
    size_t base = ((size_t)blockIdx.x * 256 + threadIdx.x) * 8;
    float4 a = *(const float4*)(W + base);
    float4 b = *(const float4*)(W + base + 4);
    uint32_t p[4];
    p[0] = pack_half2(__float2half_rn(a.x * WSCALE), __float2half_rn(a.y * WSCALE));
    p[1] = pack_half2(__float2half_rn(a.z * WSCALE), __float2half_rn(a.w * WSCALE));
    p[2] = pack_half2(__float2half_rn(b.x * WSCALE), __float2half_rn(b.y * WSCALE));
    p[3] = pack_half2(__float2half_rn(b.z * WSCALE), __float2half_rn(b.w * WSCALE));
    *(uint4*)(g_wh + base) = make_uint4(p[0], p[1], p[2], p[3]);
}

// ---------------------------------------------------------------------------
// Fused: x -> fp16 (g_xh) AND inter[m][r] = sum_k x[m][k]*a[r][k] (exact fp32)
// Each warp handles 4 m-rows: As LDS reads amortized over 4 rows (R13 version).
// ---------------------------------------------------------------------------
__global__ __launch_bounds__(256) void prep_x_kernel(
    const float* __restrict__ x,
    const float* __restrict__ lora_a)
{
    __shared__ float As[RANK][128];
    const int m0 = blockIdx.x * 32;
    const int adapter = g_adapter[m0 >> 11];
    const float* A = lora_a + (size_t)adapter * RANK * DIN;

    const int warp = threadIdx.x >> 5;
    const int lane = threadIdx.x & 31;
    const int m = m0 + warp * 4;

    float acc[4][RANK];
    #pragma unroll
    for (int w = 0; w < 4; w++)
        #pragma unroll
        for (int r = 0; r < RANK; r++) acc[w][r] = 0.0f;

    for (int k0 = 0; k0 < DIN; k0 += 128) {
        __syncthreads();
        #pragma unroll
        for (int i = threadIdx.x; i < 512; i += 256) {
            int rr = i >> 5;
            int c4 = i & 31;
            *(float4*)&As[rr][c4 * 4] =
                *(const float4*)(A + (size_t)rr * DIN + k0 + c4 * 4);
        }
        __syncthreads();

        float4 xv[4];
        #pragma unroll
        for (int w = 0; w < 4; w++) {
            xv[w] = *(const float4*)(x + (size_t)(m + w) * DIN + k0 + lane * 4);
            uint2 h = make_uint2(
                pack_half2(__float2half_rn(xv[w].x), __float2half_rn(xv[w].y)),
                pack_half2(__float2half_rn(xv[w].z), __float2half_rn(xv[w].w)));
            *(uint2*)(g_xh + (size_t)(m + w) * DIN + k0 + lane * 4) = h;
        }

        #pragma unroll
        for (int r = 0; r < RANK; r++) {
            float4 av = *(const float4*)&As[r][lane * 4];
            #pragma unroll
            for (int w = 0; w < 4; w++)
                acc[w][r] += xv[w].x * av.x + xv[w].y * av.y
                           + xv[w].z * av.z + xv[w].w * av.w;
        }
    }

    #pragma unroll
    for (int r = 0; r < RANK; r++) {
        float v0 = acc[0][r], v1 = acc[1][r], v2 = acc[2][r], v3 = acc[3][r];
        #pragma unroll
        for (int off = 16; off > 0; off >>= 1) {
            v0 += __shfl_xor_sync(0xffffffffu, v0, off);
            v1 += __shfl_xor_sync(0xffffffffu, v1, off);
            v2 += __shfl_xor_sync(0xffffffffu, v2, off);
            v3 += __shfl_xor_sync(0xffffffffu, v3, off);
        }
        if (lane == r) {
            g_inter[(size_t)m * RANK + r] = v0;
            g_inter[(size_t)(m + 1) * RANK + r] = v1;
            g_inter[(size_t)(m + 2) * RANK + r] = v2;
            g_inter[(size_t)(m + 3) * RANK + r] = v3;
        }
    }
}

// ---------------------------------------------------------------------------
// HMMA GEMM: out = (x_h @ W_h^T)/64 + LoRA + bias     (exact R12 config)
// 128x128 CTA tile, 256 threads: 8 warps of 64x32, BK=64, 3-stage pipeline
// (issue distance 2), 2 CTAs/SM back-fill each other's pipeline stalls.
// ---------------------------------------------------------------------------
__global__ __launch_bounds__(256, 2) void gemm_hmma_kernel(
    const float* __restrict__ bias,
    const float* __restrict__ lora_b,
    float* __restrict__ out)
{
    extern __shared__ char smem[];
    const uint32_t sbase = smem_u32(smem);
    const int tid  = threadIdx.x;
    const int lane = tid & 31;
    const int warp = tid >> 5;
    const int wm = warp & 1;          // 2 warps along M (64 each)
    const int wn = warp >> 1;         // 4 warps along N (32 each)
    const int n0 = blockIdx.x * BN;
    const int m0 = blockIdx.y * BM;

    const __half* Ax = g_xh + (size_t)m0 * DIN;
    const __half* Bx = g_wh + (size_t)n0 * DIN;

    // per-thread ldmatrix base offsets
    const uint32_t aoff = (uint32_t)((wm * 64 + (lane & 15)) * ROWB + (lane >> 4) * 16);
    const uint32_t boff = (uint32_t)((wn * 32 + (lane & 7) + ((lane >> 4) & 1) * 8) * ROWB
                                     + ((lane >> 3) & 1) * 16);

    float c[4][4][4];
    #pragma unroll
    for (int i = 0; i < 4; i++)
        #pragma unroll
        for (int j = 0; j < 4; j++)
            #pragma unroll
            for (int q = 0; q < 4; q++) c[i][j][q] = 0.0f;

    auto issue = [&](int it) {
        uint32_t st = sbase + (it % NSTAGE) * STAGE;
        int k0 = it * BK;
        #pragma unroll
        for (int i = 0; i < 4; i++) {               // A: 1024 chunks of 16B
            int id = tid + i * 256;
            int row = id >> 3, cc = id & 7;
            uint32_t d = st + row * ROWB + cc * 16;
            cp_async16(d + A_OFF, Ax + (size_t)row * DIN + k0 + cc * 8);
        }
        #pragma unroll
        for (int i = 0; i < 4; i++) {               // B: 1024 chunks of 16B
            int id = tid + i * 256;
            int row = id >> 3, cc = id & 7;
            uint32_t d = st + row * ROWB + cc * 16;
            cp_async16(d + B_OFF, Bx + (size_t)row * DIN + k0 + cc * 8);
        }
    };

    issue(0); CP_COMMIT();
    issue(1); CP_COMMIT();

    #pragma unroll 1
    for (int it = 0; it < NITER; it++) {
        CP_WAIT(1);
        __syncthreads();
        if (it + 2 < NITER) { issue(it + 2); CP_COMMIT(); }

        const uint32_t st = sbase + (it % NSTAGE) * STAGE;
        #pragma unroll
        for (int kk = 0; kk < 4; kk++) {
            uint32_t bh[2][4], af[4][4];
            #pragma unroll
            for (int nt = 0; nt < 2; nt++)
                LDSM4(bh[nt], st + B_OFF + boff + nt * (16 * ROWB) + kk * 32);
            #pragma unroll
            for (int i = 0; i < 4; i++)
                LDSM4(af[i], st + A_OFF + aoff + i * (16 * ROWB) + kk * 32);
            #pragma unroll
            for (int i = 0; i < 4; i++)
                #pragma unroll
                for (int nt = 0; nt < 2; nt++) {
                    MMA(c[i][2*nt],   af[i], bh[nt][0], bh[nt][1]);
                    MMA(c[i][2*nt+1], af[i], bh[nt][2], bh[nt][3]);
                }
        }
    }

    // ---- undo W scaling ----
    #pragma unroll
    for (int i = 0; i < 4; i++)
        #pragma unroll
        for (int j = 0; j < 4; j++)
            #pragma unroll
            for (int q = 0; q < 4; q++) c[i][j][q] *= WSCALE_INV;

    // ---- LoRA epilogue (exact fp32, rank 16) ----
    const int r0 = lane >> 2;
    const int cq = (lane & 3) * 2;
    const int adapter = g_adapter[m0 >> 11];
    const float* lbp = lora_b + ((size_t)adapter * DOUT + n0) * RANK;

    #pragma unroll
    for (int r = 0; r < RANK; r++) {
        float av[4][2];
        #pragma unroll
        for (int i = 0; i < 4; i++)
            #pragma unroll
            for (int h = 0; h < 2; h++)
                av[i][h] = __ldg(&g_inter[(size_t)(m0 + wm*64 + i*16 + h*8 + r0) * RANK + r]);
        float bv[4][2];
        #pragma unroll
        for (int j = 0; j < 4; j++) {
            int nl = wn * 32 + j * 8 + cq;
            bv[j][0] = __ldg(&lbp[(size_t)nl * RANK + r]);
            bv[j][1] = __ldg(&lbp[(size_t)(nl + 1) * RANK + r]);
        }
        #pragma unroll
        for (int i = 0; i < 4; i++)
            #pragma unroll
            for (int j = 0; j < 4; j++) {
                c[i][j][0] += av[i][0] * bv[j][0];
                c[i][j][1] += av[i][0] * bv[j][1];
                c[i][j][2] += av[i][1] * bv[j][0];
                c[i][j][3] += av[i][1] * bv[j][1];
            }
    }

    // ---- bias + writeback ----
    #pragma unroll
    for (int j = 0; j < 4; j++) {
        int n = n0 + wn * 32 + j * 8 + cq;
        float b0 = __ldg(bias + n);
        float b1 = __ldg(bias + n + 1);
        #pragma unroll
        for (int i = 0; i < 4; i++) {
            int m = m0 + wm * 64 + i * 16 + r0;
            *(float2*)(out + (size_t)m * DOUT + n) =
                make_float2(c[i][j][0] + b0, c[i][j][1] + b1);
            *(float2*)(out + (size_t)(m + 8) * DOUT + n) =
                make_float2(c[i][j][2] + b0, c[i][j][3] + b1);
        }
    }
}

// ---------------------------------------------------------------------------
extern "C" void kernel_launch(void* const* d_in, const int* in_sizes, int n_in,
                              void* d_out, int out_size) {
    const float* x       = (const float*)d_in[0];
    const float* W       = (const float*)d_in[1];
    const float* bias    = (const float*)d_in[2];
    const float* lora_a  = (const float*)d_in[3];
    const float* lora_b  = (const float*)d_in[4];
    const int*   idx_raw = (const int*)d_in[5];
    float* out = (float*)d_out;

    cudaFuncSetAttribute(gemm_hmma_kernel,
                         cudaFuncAttributeMaxDynamicSharedMemorySize, SMEM_TOTAL);

    setup_adapters_kernel<<<1, 1>>>(idx_raw);
    convert_w_kernel<<<(int)(((size_t)DOUT * DIN) / 2048), 256>>>(W);
    prep_x_kernel<<<MROWS / 32, 256>>>(x, lora_a);

    dim3 grid(DOUT / BN, MROWS / BM);   // (32, 128): N fastest -> X reuse, W streams
    gemm_hmma_kernel<<<grid, 256, SMEM_TOTAL>>>(bias, lora_b, out);
}

// round 15
// speedup vs baseline: 1.0776x; 1.0091x over previous
#include <cuda_runtime.h>
#include <cuda_fp16.h>
#include <cstdint>

#define BATCH 8
#define SEQ 2048
#define DIN 4096
#define DOUT 4096
#define RANK 16
#define NADAPT 8
#define MROWS (BATCH * SEQ)   // 16384

// GEMM tiling: 128x128 CTA tile, 2 CTAs per SM (measured optimum)
#define BM 128
#define BN 128
#define BK 64
#define NITER (DIN / BK)      // 64
#define ROWB 144              // 64 fp16 = 128B data + 16B pad
#define A_OFF 0
#define B_OFF 18432           // 128*144
#define STAGE 36864           // + 128*144
#define NSTAGE 3
#define SMEM_TOTAL (NSTAGE * STAGE)   // 110592/CTA -> 2 CTAs = 221184/SM
#define WSCALE 64.0f
#define WSCALE_INV 0.015625f

// fused prep grid split
#define XBLOCKS (MROWS / 32)                        // 512 (x+inter blocks)
#define WBLOCKS ((DOUT * DIN) / 2048)               // 8192 (W convert blocks)

// ---------------- device scratch (no cudaMalloc allowed) -------------------
__device__ int    g_adapter[BATCH];
__device__ float  g_inter[(size_t)MROWS * RANK];
__device__ __half g_xh[(size_t)MROWS * DIN];
__device__ __half g_wh[(size_t)DOUT * DIN];

// ---------------- PTX helpers ----------------------------------------------
__device__ __forceinline__ uint32_t smem_u32(const void* p) {
    uint32_t a;
    asm("{ .reg .u64 t; cvta.to.shared.u64 t, %1; cvt.u32.u64 %0, t; }"
        : "=r"(a) : "l"(p));
    return a;
}
__device__ __forceinline__ void cp_async16(uint32_t dst, const void* src) {
    asm volatile("cp.async.cg.shared.global [%0], [%1], 16;"
                 :: "r"(dst), "l"(src) : "memory");
}
#define CP_COMMIT() asm volatile("cp.async.commit_group;" ::: "memory")
#define CP_WAIT(N)  asm volatile("cp.async.wait_group %0;" :: "n"(N) : "memory")

#define LDSM4(r, addr) \
    asm volatile("ldmatrix.sync.aligned.m8n8.x4.shared.b16 {%0,%1,%2,%3}, [%4];" \
                 : "=r"((r)[0]), "=r"((r)[1]), "=r"((r)[2]), "=r"((r)[3]) \
                 : "r"(addr))

#define MMA(d, a, b0, b1) \
    asm volatile("mma.sync.aligned.m16n8k16.row.col.f32.f16.f16.f32 " \
                 "{%0,%1,%2,%3}, {%4,%5,%6,%7}, {%8,%9}, {%0,%1,%2,%3};" \
                 : "+f"((d)[0]), "+f"((d)[1]), "+f"((d)[2]), "+f"((d)[3]) \
                 : "r"((a)[0]), "r"((a)[1]), "r"((a)[2]), "r"((a)[3]), \
                   "r"(b0), "r"(b1))

__device__ __forceinline__ uint32_t pack_half2(__half a, __half b) {
    return (uint32_t)__half_as_ushort(a) | ((uint32_t)__half_as_ushort(b) << 16);
}

// ---------------------------------------------------------------------------
// Setup: normalize adapter indices (int64 or int32, robustly)
// ---------------------------------------------------------------------------
__global__ void setup_adapters_kernel(const int* __restrict__ idx_raw) {
    if (threadIdx.x != 0 || blockIdx.x != 0) return;
    bool is64 = true;
    #pragma unroll
    for (int b = 0; b < BATCH; b++) {
        int lo = idx_raw[2 * b];
        int hi = idx_raw[2 * b + 1];
        if (hi != 0 || lo < 0 || lo >= NADAPT) { is64 = false; break; }
    }
    #pragma unroll
    for (int b = 0; b < BATCH; b++) {
        int v = is64 ? idx_raw[2 * b] : idx_raw[b];
        if (v < 0) v = 0;
        if (v >= NADAPT) v = NADAPT - 1;
        g_adapter[b] = v;
    }
}

// ---------------------------------------------------------------------------
// Fused prep: blocks [0, XBLOCKS) convert x->fp16 AND compute inter (LDS-heavy);
// blocks [XBLOCKS, XBLOCKS+WBLOCKS) convert W*64->fp16 (pure DRAM stream).
// The W blocks fill SM slots left idle by the x blocks' LDS phases.
// ---------------------------------------------------------------------------
__global__ __launch_bounds__(256) void prep_fused_kernel(
    const float* __restrict__ x,
    const float* __restrict__ lora_a,
    const float* __restrict__ W)
{
    if (blockIdx.x >= XBLOCKS) {
        // ---- W convert: 2048 elems per block ----
        size_t base = ((size_t)(blockIdx.x - XBLOCKS) * 256 + threadIdx.x) * 8;
        float4 a = *(const float4*)(W + base);
        float4 b = *(const float4*)(W + base + 4);
        uint32_t p[4];
        p[0] = pack_half2(__float2half_rn(a.x * WSCALE), __float2half_rn(a.y * WSCALE));
        p[1] = pack_half2(__float2half_rn(a.z * WSCALE), __float2half_rn(a.w * WSCALE));
        p[2] = pack_half2(__float2half_rn(b.x * WSCALE), __float2half_rn(b.y * WSCALE));
        p[3] = pack_half2(__float2half_rn(b.z * WSCALE), __float2half_rn(b.w * WSCALE));
        *(uint4*)(g_wh + base) = make_uint4(p[0], p[1], p[2], p[3]);
        return;
    }

    // ---- x convert + inter: 32 rows per block, 4 rows per warp ----
    __shared__ float As[RANK][128];
    const int m0 = blockIdx.x * 32;
    const int adapter = g_adapter[m0 >> 11];
    const float* A = lora_a + (size_t)adapter * RANK * DIN;

    const int warp = threadIdx.x >> 5;
    const int lane = threadIdx.x & 31;
    const int m = m0 + warp * 4;

    float acc[4][RANK];
    #pragma unroll
    for (int w = 0; w < 4; w++)
        #pragma unroll
        for (int r = 0; r < RANK; r++) acc[w][r] = 0.0f;

    for (int k0 = 0; k0 < DIN; k0 += 128) {
        __syncthreads();
        #pragma unroll
        for (int i = threadIdx.x; i < 512; i += 256) {
            int rr = i >> 5;
            int c4 = i & 31;
            *(float4*)&As[rr][c4 * 4] =
                *(const float4*)(A + (size_t)rr * DIN + k0 + c4 * 4);
        }
        __syncthreads();

        float4 xv[4];
        #pragma unroll
        for (int w = 0; w < 4; w++) {
            xv[w] = *(const float4*)(x + (size_t)(m + w) * DIN + k0 + lane * 4);
            uint2 h = make_uint2(
                pack_half2(__float2half_rn(xv[w].x), __float2half_rn(xv[w].y)),
                pack_half2(__float2half_rn(xv[w].z), __float2half_rn(xv[w].w)));
            *(uint2*)(g_xh + (size_t)(m + w) * DIN + k0 + lane * 4) = h;
        }

        #pragma unroll
        for (int r = 0; r < RANK; r++) {
            float4 av = *(const float4*)&As[r][lane * 4];
            #pragma unroll
            for (int w = 0; w < 4; w++)
                acc[w][r] += xv[w].x * av.x + xv[w].y * av.y
                           + xv[w].z * av.z + xv[w].w * av.w;
        }
    }

    #pragma unroll
    for (int r = 0; r < RANK; r++) {
        float v0 = acc[0][r], v1 = acc[1][r], v2 = acc[2][r], v3 = acc[3][r];
        #pragma unroll
        for (int off = 16; off > 0; off >>= 1) {
            v0 += __shfl_xor_sync(0xffffffffu, v0, off);
            v1 += __shfl_xor_sync(0xffffffffu, v1, off);
            v2 += __shfl_xor_sync(0xffffffffu, v2, off);
            v3 += __shfl_xor_sync(0xffffffffu, v3, off);
        }
        if (lane == r) {
            g_inter[(size_t)m * RANK + r] = v0;
            g_inter[(size_t)(m + 1) * RANK + r] = v1;
            g_inter[(size_t)(m + 2) * RANK + r] = v2;
            g_inter[(size_t)(m + 3) * RANK + r] = v3;
        }
    }
}

// ---------------------------------------------------------------------------
// HMMA GEMM: out = (x_h @ W_h^T)/64 + LoRA + bias     (measured-optimal config)
// 128x128 CTA tile, 256 threads: 8 warps of 64x32, BK=64, 3-stage pipeline
// (issue distance 2), 2 CTAs/SM.
// ---------------------------------------------------------------------------
__global__ __launch_bounds__(256, 2) void gemm_hmma_kernel(
    const float* __restrict__ bias,
    const float* __restrict__ lora_b,
    float* __restrict__ out)
{
    extern __shared__ char smem[];
    const uint32_t sbase = smem_u32(smem);
    const int tid  = threadIdx.x;
    const int lane = tid & 31;
    const int warp = tid >> 5;
    const int wm = warp & 1;          // 2 warps along M (64 each)
    const int wn = warp >> 1;         // 4 warps along N (32 each)
    const int n0 = blockIdx.x * BN;
    const int m0 = blockIdx.y * BM;

    const __half* Ax = g_xh + (size_t)m0 * DIN;
    const __half* Bx = g_wh + (size_t)n0 * DIN;

    const uint32_t aoff = (uint32_t)((wm * 64 + (lane & 15)) * ROWB + (lane >> 4) * 16);
    const uint32_t boff = (uint32_t)((wn * 32 + (lane & 7) + ((lane >> 4) & 1) * 8) * ROWB
                                     + ((lane >> 3) & 1) * 16);

    float c[4][4][4];
    #pragma unroll
    for (int i = 0; i < 4; i++)
        #pragma unroll
        for (int j = 0; j < 4; j++)
            #pragma unroll
            for (int q = 0; q < 4; q++) c[i][j][q] = 0.0f;

    auto issue = [&](int it) {
        uint32_t st = sbase + (it % NSTAGE) * STAGE;
        int k0 = it * BK;
        #pragma unroll
        for (int i = 0; i < 4; i++) {               // A: 1024 chunks of 16B
            int id = tid + i * 256;
            int row = id >> 3, cc = id & 7;
            uint32_t d = st + row * ROWB + cc * 16;
            cp_async16(d + A_OFF, Ax + (size_t)row * DIN + k0 + cc * 8);
        }
        #pragma unroll
        for (int i = 0; i < 4; i++) {               // B: 1024 chunks of 16B
            int id = tid + i * 256;
            int row = id >> 3, cc = id & 7;
            uint32_t d = st + row * ROWB + cc * 16;
            cp_async16(d + B_OFF, Bx + (size_t)row * DIN + k0 + cc * 8);
        }
    };

    issue(0); CP_COMMIT();
    issue(1); CP_COMMIT();

    #pragma unroll 1
    for (int it = 0; it < NITER; it++) {
        CP_WAIT(1);
        __syncthreads();
        if (it + 2 < NITER) { issue(it + 2); CP_COMMIT(); }

        const uint32_t st = sbase + (it % NSTAGE) * STAGE;
        #pragma unroll
        for (int kk = 0; kk < 4; kk++) {
            uint32_t bh[2][4], af[4][4];
            #pragma unroll
            for (int nt = 0; nt < 2; nt++)
                LDSM4(bh[nt], st + B_OFF + boff + nt * (16 * ROWB) + kk * 32);
            #pragma unroll
            for (int i = 0; i < 4; i++)
                LDSM4(af[i], st + A_OFF + aoff + i * (16 * ROWB) + kk * 32);
            #pragma unroll
            for (int i = 0; i < 4; i++)
                #pragma unroll
                for (int nt = 0; nt < 2; nt++) {
                    MMA(c[i][2*nt],   af[i], bh[nt][0], bh[nt][1]);
                    MMA(c[i][2*nt+1], af[i], bh[nt][2], bh[nt][3]);
                }
        }
    }

    // ---- undo W scaling ----
    #pragma unroll
    for (int i = 0; i < 4; i++)
        #pragma unroll
        for (int j = 0; j < 4; j++)
            #pragma unroll
            for (int q = 0; q < 4; q++) c[i][j][q] *= WSCALE_INV;

    // ---- LoRA epilogue (exact fp32, rank 16) ----
    const int r0 = lane >> 2;
    const int cq = (lane & 3) * 2;
    const int adapter = g_adapter[m0 >> 11];
    const float* lbp = lora_b + ((size_t)adapter * DOUT + n0) * RANK;

    #pragma unroll
    for (int r = 0; r < RANK; r++) {
        float av[4][2];
        #pragma unroll
        for (int i = 0; i < 4; i++)
            #pragma unroll
            for (int h = 0; h < 2; h++)
                av[i][h] = __ldg(&g_inter[(size_t)(m0 + wm*64 + i*16 + h*8 + r0) * RANK + r]);
        float bv[4][2];
        #pragma unroll
        for (int j = 0; j < 4; j++) {
            int nl = wn * 32 + j * 8 + cq;
            bv[j][0] = __ldg(&lbp[(size_t)nl * RANK + r]);
            bv[j][1] = __ldg(&lbp[(size_t)(nl + 1) * RANK + r]);
        }
        #pragma unroll
        for (int i = 0; i < 4; i++)
            #pragma unroll
            for (int j = 0; j < 4; j++) {
                c[i][j][0] += av[i][0] * bv[j][0];
                c[i][j][1] += av[i][0] * bv[j][1];
                c[i][j][2] += av[i][1] * bv[j][0];
                c[i][j][3] += av[i][1] * bv[j][1];
            }
    }

    // ---- bias + writeback ----
    #pragma unroll
    for (int j = 0; j < 4; j++) {
        int n = n0 + wn * 32 + j * 8 + cq;
        float b0 = __ldg(bias + n);
        float b1 = __ldg(bias + n + 1);
        #pragma unroll
        for (int i = 0; i < 4; i++) {
            int m = m0 + wm * 64 + i * 16 + r0;
            *(float2*)(out + (size_t)m * DOUT + n) =
                make_float2(c[i][j][0] + b0, c[i][j][1] + b1);
            *(float2*)(out + (size_t)(m + 8) * DOUT + n) =
                make_float2(c[i][j][2] + b0, c[i][j][3] + b1);
        }
    }
}

// ---------------------------------------------------------------------------
extern "C" void kernel_launch(void* const* d_in, const int* in_sizes, int n_in,
                              void* d_out, int out_size) {
    const float* x       = (const float*)d_in[0];
    const float* W       = (const float*)d_in[1];
    const float* bias    = (const float*)d_in[2];
    const float* lora_a  = (const float*)d_in[3];
    const float* lora_b  = (const float*)d_in[4];
    const int*   idx_raw = (const int*)d_in[5];
    float* out = (float*)d_out;

    cudaFuncSetAttribute(gemm_hmma_kernel,
                         cudaFuncAttributeMaxDynamicSharedMemorySize, SMEM_TOTAL);

    setup_adapters_kernel<<<1, 1>>>(idx_raw);
    prep_fused_kernel<<<XBLOCKS + WBLOCKS, 256>>>(x, lora_a, W);

    dim3 grid(DOUT / BN, MROWS / BM);   // (32, 128): N fastest -> X reuse, W streams
    gemm_hmma_kernel<<<grid, 256, SMEM_TOTAL>>>(bias, lora_b, out);
}

// round 16
// speedup vs baseline: 1.0841x; 1.0060x over previous
#include <cuda_runtime.h>
#include <cuda_fp16.h>
#include <cstdint>

#define BATCH 8
#define SEQ 2048
#define DIN 4096
#define DOUT 4096
#define RANK 16
#define NADAPT 8
#define MROWS (BATCH * SEQ)   // 16384

// GEMM tiling: 128x128 CTA tile, 2 CTAs per SM (measured optimum)
#define BM 128
#define BN 128
#define BK 64
#define NITER (DIN / BK)      // 64
#define ROWB 144              // 64 fp16 = 128B data + 16B pad
#define A_OFF 0
#define B_OFF 18432           // 128*144
#define STAGE 36864           // + 128*144
#define NSTAGE 3
#define SMEM_TOTAL (NSTAGE * STAGE)   // 110592/CTA -> 2 CTAs = 221184/SM
#define WSCALE 64.0f
#define WSCALE_INV 0.015625f

// fused prep grid split
#define XBLOCKS (MROWS / 32)                        // 512 (x+inter blocks)
#define WELEMS_PER_BLOCK 8192                       // 32 elems/thread... 8 f32/thread x 4
#define WBLOCKS ((DOUT * DIN) / WELEMS_PER_BLOCK)   // 2048 (W convert blocks)

// ---------------- device scratch (no cudaMalloc allowed) -------------------
__device__ float  g_inter[(size_t)MROWS * RANK];
__device__ __half g_xh[(size_t)MROWS * DIN];
__device__ __half g_wh[(size_t)DOUT * DIN];

// ---------------- PTX helpers ----------------------------------------------
__device__ __forceinline__ uint32_t smem_u32(const void* p) {
    uint32_t a;
    asm("{ .reg .u64 t; cvta.to.shared.u64 t, %1; cvt.u32.u64 %0, t; }"
        : "=r"(a) : "l"(p));
    return a;
}
__device__ __forceinline__ void cp_async16(uint32_t dst, const void* src) {
    asm volatile("cp.async.cg.shared.global [%0], [%1], 16;"
                 :: "r"(dst), "l"(src) : "memory");
}
#define CP_COMMIT() asm volatile("cp.async.commit_group;" ::: "memory")
#define CP_WAIT(N)  asm volatile("cp.async.wait_group %0;" :: "n"(N) : "memory")

#define LDSM4(r, addr) \
    asm volatile("ldmatrix.sync.aligned.m8n8.x4.shared.b16 {%0,%1,%2,%3}, [%4];" \
                 : "=r"((r)[0]), "=r"((r)[1]), "=r"((r)[2]), "=r"((r)[3]) \
                 : "r"(addr))

#define MMA(d, a, b0, b1) \
    asm volatile("mma.sync.aligned.m16n8k16.row.col.f32.f16.f16.f32 " \
                 "{%0,%1,%2,%3}, {%4,%5,%6,%7}, {%8,%9}, {%0,%1,%2,%3};" \
                 : "+f"((d)[0]), "+f"((d)[1]), "+f"((d)[2]), "+f"((d)[3]) \
                 : "r"((a)[0]), "r"((a)[1]), "r"((a)[2]), "r"((a)[3]), \
                   "r"(b0), "r"(b1))

__device__ __forceinline__ uint32_t pack_half2(__half a, __half b) {
    return (uint32_t)__half_as_ushort(a) | ((uint32_t)__half_as_ushort(b) << 16);
}

// Inline adapter resolution: identical deterministic logic in every caller.
// idx_raw is either int64 (pairs [lo,hi] with hi==0, lo in [0,8)) or int32.
__device__ __forceinline__ int resolve_adapter(const int* __restrict__ idx_raw,
                                               int batch) {
    bool is64 = true;
    #pragma unroll
    for (int b = 0; b < BATCH; b++) {
        int lo = idx_raw[2 * b];
        int hi = idx_raw[2 * b + 1];
        if (hi != 0 || lo < 0 || lo >= NADAPT) { is64 = false; break; }
    }
    int v = is64 ? idx_raw[2 * batch] : idx_raw[batch];
    if (v < 0) v = 0;
    if (v >= NADAPT) v = NADAPT - 1;
    return v;
}

// ---------------------------------------------------------------------------
// Fused prep: blocks [0, XBLOCKS) convert x->fp16 AND compute inter (LDS-heavy);
// blocks [XBLOCKS, XBLOCKS+WBLOCKS) convert W*64->fp16 (pure DRAM stream,
// 32 elems/thread -> high MLP, few waves).
// ---------------------------------------------------------------------------
__global__ __launch_bounds__(256) void prep_fused_kernel(
    const float* __restrict__ x,
    const float* __restrict__ lora_a,
    const float* __restrict__ W,
    const int* __restrict__ idx_raw)
{
    if (blockIdx.x >= XBLOCKS) {
        // ---- W convert: 8192 elems per block, 32 per thread ----
        size_t base = (size_t)(blockIdx.x - XBLOCKS) * WELEMS_PER_BLOCK
                      + (size_t)threadIdx.x * 8;
        #pragma unroll
        for (int rep = 0; rep < 4; rep++) {
            size_t o = base + (size_t)rep * 2048;
            float4 a = *(const float4*)(W + o);
            float4 b = *(const float4*)(W + o + 4);
            uint32_t p[4];
            p[0] = pack_half2(__float2half_rn(a.x * WSCALE), __float2half_rn(a.y * WSCALE));
            p[1] = pack_half2(__float2half_rn(a.z * WSCALE), __float2half_rn(a.w * WSCALE));
            p[2] = pack_half2(__float2half_rn(b.x * WSCALE), __float2half_rn(b.y * WSCALE));
            p[3] = pack_half2(__float2half_rn(b.z * WSCALE), __float2half_rn(b.w * WSCALE));
            *(uint4*)(g_wh + o) = make_uint4(p[0], p[1], p[2], p[3]);
        }
        return;
    }

    // ---- x convert + inter: 32 rows per block, 4 rows per warp ----
    __shared__ float As[RANK][128];
    const int m0 = blockIdx.x * 32;
    const int adapter = resolve_adapter(idx_raw, m0 >> 11);
    const float* A = lora_a + (size_t)adapter * RANK * DIN;

    const int warp = threadIdx.x >> 5;
    const int lane = threadIdx.x & 31;
    const int m = m0 + warp * 4;

    float acc[4][RANK];
    #pragma unroll
    for (int w = 0; w < 4; w++)
        #pragma unroll
        for (int r = 0; r < RANK; r++) acc[w][r] = 0.0f;

    for (int k0 = 0; k0 < DIN; k0 += 128) {
        __syncthreads();
        #pragma unroll
        for (int i = threadIdx.x; i < 512; i += 256) {
            int rr = i >> 5;
            int c4 = i & 31;
            *(float4*)&As[rr][c4 * 4] =
                *(const float4*)(A + (size_t)rr * DIN + k0 + c4 * 4);
        }
        __syncthreads();

        float4 xv[4];
        #pragma unroll
        for (int w = 0; w < 4; w++) {
            xv[w] = *(const float4*)(x + (size_t)(m + w) * DIN + k0 + lane * 4);
            uint2 h = make_uint2(
                pack_half2(__float2half_rn(xv[w].x), __float2half_rn(xv[w].y)),
                pack_half2(__float2half_rn(xv[w].z), __float2half_rn(xv[w].w)));
            *(uint2*)(g_xh + (size_t)(m + w) * DIN + k0 + lane * 4) = h;
        }

        #pragma unroll
        for (int r = 0; r < RANK; r++) {
            float4 av = *(const float4*)&As[r][lane * 4];
            #pragma unroll
            for (int w = 0; w < 4; w++)
                acc[w][r] += xv[w].x * av.x + xv[w].y * av.y
                           + xv[w].z * av.z + xv[w].w * av.w;
        }
    }

    #pragma unroll
    for (int r = 0; r < RANK; r++) {
        float v0 = acc[0][r], v1 = acc[1][r], v2 = acc[2][r], v3 = acc[3][r];
        #pragma unroll
        for (int off = 16; off > 0; off >>= 1) {
            v0 += __shfl_xor_sync(0xffffffffu, v0, off);
            v1 += __shfl_xor_sync(0xffffffffu, v1, off);
            v2 += __shfl_xor_sync(0xffffffffu, v2, off);
            v3 += __shfl_xor_sync(0xffffffffu, v3, off);
        }
        if (lane == r) {
            g_inter[(size_t)m * RANK + r] = v0;
            g_inter[(size_t)(m + 1) * RANK + r] = v1;
            g_inter[(size_t)(m + 2) * RANK + r] = v2;
            g_inter[(size_t)(m + 3) * RANK + r] = v3;
        }
    }
}

// ---------------------------------------------------------------------------
// HMMA GEMM: out = (x_h @ W_h^T)/64 + LoRA + bias     (measured-optimal config)
// 128x128 CTA tile, 256 threads: 8 warps of 64x32, BK=64, 3-stage pipeline
// (issue distance 2), 2 CTAs/SM.
// ---------------------------------------------------------------------------
__global__ __launch_bounds__(256, 2) void gemm_hmma_kernel(
    const float* __restrict__ bias,
    const float* __restrict__ lora_b,
    float* __restrict__ out,
    const int* __restrict__ idx_raw)
{
    extern __shared__ char smem[];
    const uint32_t sbase = smem_u32(smem);
    const int tid  = threadIdx.x;
    const int lane = tid & 31;
    const int warp = tid >> 5;
    const int wm = warp & 1;          // 2 warps along M (64 each)
    const int wn = warp >> 1;         // 4 warps along N (32 each)
    const int n0 = blockIdx.x * BN;
    const int m0 = blockIdx.y * BM;

    const __half* Ax = g_xh + (size_t)m0 * DIN;
    const __half* Bx = g_wh + (size_t)n0 * DIN;

    const uint32_t aoff = (uint32_t)((wm * 64 + (lane & 15)) * ROWB + (lane >> 4) * 16);
    const uint32_t boff = (uint32_t)((wn * 32 + (lane & 7) + ((lane >> 4) & 1) * 8) * ROWB
                                     + ((lane >> 3) & 1) * 16);

    float c[4][4][4];
    #pragma unroll
    for (int i = 0; i < 4; i++)
        #pragma unroll
        for (int j = 0; j < 4; j++)
            #pragma unroll
            for (int q = 0; q < 4; q++) c[i][j][q] = 0.0f;

    auto issue = [&](int it) {
        uint32_t st = sbase + (it % NSTAGE) * STAGE;
        int k0 = it * BK;
        #pragma unroll
        for (int i = 0; i < 4; i++) {               // A: 1024 chunks of 16B
            int id = tid + i * 256;
            int row = id >> 3, cc = id & 7;
            uint32_t d = st + row * ROWB + cc * 16;
            cp_async16(d + A_OFF, Ax + (size_t)row * DIN + k0 + cc * 8);
        }
        #pragma unroll
        for (int i = 0; i < 4; i++) {               // B: 1024 chunks of 16B
            int id = tid + i * 256;
            int row = id >> 3, cc = id & 7;
            uint32_t d = st + row * ROWB + cc * 16;
            cp_async16(d + B_OFF, Bx + (size_t)row * DIN + k0 + cc * 8);
        }
    };

    issue(0); CP_COMMIT();
    issue(1); CP_COMMIT();

    #pragma unroll 1
    for (int it = 0; it < NITER; it++) {
        CP_WAIT(1);
        __syncthreads();
        if (it + 2 < NITER) { issue(it + 2); CP_COMMIT(); }

        const uint32_t st = sbase + (it % NSTAGE) * STAGE;
        #pragma unroll
        for (int kk = 0; kk < 4; kk++) {
            uint32_t bh[2][4], af[4][4];
            #pragma unroll
            for (int nt = 0; nt < 2; nt++)
                LDSM4(bh[nt], st + B_OFF + boff + nt * (16 * ROWB) + kk * 32);
            #pragma unroll
            for (int i = 0; i < 4; i++)
                LDSM4(af[i], st + A_OFF + aoff + i * (16 * ROWB) + kk * 32);
            #pragma unroll
            for (int i = 0; i < 4; i++)
                #pragma unroll
                for (int nt = 0; nt < 2; nt++) {
                    MMA(c[i][2*nt],   af[i], bh[nt][0], bh[nt][1]);
                    MMA(c[i][2*nt+1], af[i], bh[nt][2], bh[nt][3]);
                }
        }
    }

    // ---- undo W scaling ----
    #pragma unroll
    for (int i = 0; i < 4; i++)
        #pragma unroll
        for (int j = 0; j < 4; j++)
            #pragma unroll
            for (int q = 0; q < 4; q++) c[i][j][q] *= WSCALE_INV;

    // ---- LoRA epilogue (exact fp32, rank 16) ----
    const int r0 = lane >> 2;
    const int cq = (lane & 3) * 2;
    const int adapter = resolve_adapter(idx_raw, m0 >> 11);
    const float* lbp = lora_b + ((size_t)adapter * DOUT + n0) * RANK;

    #pragma unroll
    for (int r = 0; r < RANK; r++) {
        float av[4][2];
        #pragma unroll
        for (int i = 0; i < 4; i++)
            #pragma unroll
            for (int h = 0; h < 2; h++)
                av[i][h] = __ldg(&g_inter[(size_t)(m0 + wm*64 + i*16 + h*8 + r0) * RANK + r]);
        float bv[4][2];
        #pragma unroll
        for (int j = 0; j < 4; j++) {
            int nl = wn * 32 + j * 8 + cq;
            bv[j][0] = __ldg(&lbp[(size_t)nl * RANK + r]);
            bv[j][1] = __ldg(&lbp[(size_t)(nl + 1) * RANK + r]);
        }
        #pragma unroll
        for (int i = 0; i < 4; i++)
            #pragma unroll
            for (int j = 0; j < 4; j++) {
                c[i][j][0] += av[i][0] * bv[j][0];
                c[i][j][1] += av[i][0] * bv[j][1];
                c[i][j][2] += av[i][1] * bv[j][0];
                c[i][j][3] += av[i][1] * bv[j][1];
            }
    }

    // ---- bias + writeback ----
    #pragma unroll
    for (int j = 0; j < 4; j++) {
        int n = n0 + wn * 32 + j * 8 + cq;
        float b0 = __ldg(bias + n);
        float b1 = __ldg(bias + n + 1);
        #pragma unroll
        for (int i = 0; i < 4; i++) {
            int m = m0 + wm * 64 + i * 16 + r0;
            *(float2*)(out + (size_t)m * DOUT + n) =
                make_float2(c[i][j][0] + b0, c[i][j][1] + b1);
            *(float2*)(out + (size_t)(m + 8) * DOUT + n) =
                make_float2(c[i][j][2] + b0, c[i][j][3] + b1);
        }
    }
}

// ---------------------------------------------------------------------------
extern "C" void kernel_launch(void* const* d_in, const int* in_sizes, int n_in,
                              void* d_out, int out_size) {
    const float* x       = (const float*)d_in[0];
    const float* W       = (const float*)d_in[1];
    const float* bias    = (const float*)d_in[2];
    const float* lora_a  = (const float*)d_in[3];
    const float* lora_b  = (const float*)d_in[4];
    const int*   idx_raw = (const int*)d_in[5];
    float* out = (float*)d_out;

    cudaFuncSetAttribute(gemm_hmma_kernel,
                         cudaFuncAttributeMaxDynamicSharedMemorySize, SMEM_TOTAL);

    prep_fused_kernel<<<XBLOCKS + WBLOCKS, 256>>>(x, lora_a, W, idx_raw);

    dim3 grid(DOUT / BN, MROWS / BM);   // (32, 128): N fastest -> X reuse, W streams
    gemm_hmma_kernel<<<grid, 256, SMEM_TOTAL>>>(bias, lora_b, out, idx_raw);
}